// round 3
// baseline (speedup 1.0000x reference)
#include <cuda_runtime.h>
#include <cuda_bf16.h>
#include <math.h>

// ---------------------------------------------------------------------------
// Problem constants
// ---------------------------------------------------------------------------
#define BDIM   8192
#define DDIM   1024
#define HDIM   2048
#define H2DIM  1024
#define CDIM   1000
#define KDIM   128
#define EDIM   8
#define TOPK   2
#define MAXROWS (BDIM * TOPK)   // 16384 grouped rows

// ---------------------------------------------------------------------------
// Scratch (device globals — no allocation allowed)
// ---------------------------------------------------------------------------
__device__ float g_h    [(size_t)BDIM * HDIM];     // relu(x@fw1+fb1)
__device__ float g_feats[(size_t)BDIM * HDIM];     // feats
__device__ float g_pk   [(size_t)BDIM * KDIM];     // feats@kw+kb (pre-norm)
__device__ float g_keysn[EDIM * KDIM];             // normalized keys
__device__ float g_sim  [BDIM * EDIM];
__device__ float g_weights[BDIM * EDIM];
__device__ float g_wslot[BDIM * TOPK];             // softmax weights per slot
__device__ int   g_topi [BDIM * TOPK];
__device__ int   g_counts[EDIM];
__device__ int   g_offsets[EDIM + 1];
__device__ int   g_cursor[EDIM];
__device__ int   g_list [MAXROWS];                 // token ids grouped by expert
__device__ int   g_pos  [BDIM * TOPK];             // grouped row of (token,slot)
__device__ float g_h1   [(size_t)MAXROWS * HDIM];  // 128 MB
__device__ float g_h2   [(size_t)MAXROWS * H2DIM]; // 64 MB
__device__ float g_eout [(size_t)MAXROWS * CDIM];  // 64 MB

// ---------------------------------------------------------------------------
// Tiled fp32 GEMM:  C = act(A[M,Kd] @ W[Kd,N] + bias)
// STAGE: 0 x->g_h  1 g_h->g_feats  2 g_feats->g_pk
//        3 expert1 (gather g_feats via g_list) -> g_h1
//        4 expert2 (g_h1 contiguous)           -> g_h2
//        5 expert3 (g_h2 contiguous)           -> g_eout
// ---------------------------------------------------------------------------
#define BM 128
#define BN 128
#define BK 16
#define TM 8
#define TN 8

template<int STAGE, bool RELU>
__global__ __launch_bounds__(256) void gemm_k(const float* __restrict__ Aext,
                                              const float* __restrict__ W,
                                              const float* __restrict__ Bias,
                                              int M, int N, int Kd)
{
    const float* A;
    float* C;
    const int* gather = nullptr;

    if (STAGE == 0)      { A = Aext;    C = g_h;     }
    else if (STAGE == 1) { A = g_h;     C = g_feats; }
    else if (STAGE == 2) { A = g_feats; C = g_pk;    }
    else {
        int e  = blockIdx.z;
        int m0 = g_offsets[e];
        M = g_offsets[e + 1] - m0;
        W    += (size_t)e * Kd * N;
        Bias += (size_t)e * N;
        if (STAGE == 3)      { A = g_feats; gather = g_list + m0; C = g_h1   + (size_t)m0 * N; }
        else if (STAGE == 4) { A = g_h1  + (size_t)m0 * Kd;       C = g_h2   + (size_t)m0 * N; }
        else                 { A = g_h2  + (size_t)m0 * Kd;       C = g_eout + (size_t)m0 * N; }
    }

    const int tileM = blockIdx.y * BM;
    const int tileN = blockIdx.x * BN;
    if (tileM >= M) return;

    __shared__ float As[BK][BM];
    __shared__ float Bs[BK][BN];

    const int tid = threadIdx.x;
    const int ty  = tid >> 4;   // 0..15
    const int tx  = tid & 15;   // 0..15

    float acc[TM][TN];
#pragma unroll
    for (int i = 0; i < TM; i++)
#pragma unroll
        for (int j = 0; j < TN; j++) acc[i][j] = 0.f;

    for (int k0 = 0; k0 < Kd; k0 += BK) {
        // --- load A tile (BM x BK), store transposed As[k][m] ---
#pragma unroll
        for (int it = 0; it < 2; it++) {
            int r = (tid >> 2) + it * 64;      // 0..127
            int c = (tid & 3) * 4;             // 0..12
            int grow = tileM + r;
            float4 v = make_float4(0.f, 0.f, 0.f, 0.f);
            if (grow < M) {
                size_t arow = (STAGE == 3) ? (size_t)gather[grow] : (size_t)grow;
                v = *(const float4*)(A + arow * Kd + k0 + c);
            }
            As[c + 0][r] = v.x; As[c + 1][r] = v.y;
            As[c + 2][r] = v.z; As[c + 3][r] = v.w;
        }
        // --- load W tile (BK x BN) ---
#pragma unroll
        for (int it = 0; it < 2; it++) {
            int r = (tid >> 5) + it * 8;       // 0..15
            int c = (tid & 31) * 4;            // 0..124
            int gcol = tileN + c;
            float4 v = make_float4(0.f, 0.f, 0.f, 0.f);
            const float* wp = W + (size_t)(k0 + r) * N + gcol;
            if (gcol + 3 < N) {
                v = *(const float4*)wp;
            } else {
                if (gcol + 0 < N) v.x = wp[0];
                if (gcol + 1 < N) v.y = wp[1];
                if (gcol + 2 < N) v.z = wp[2];
                if (gcol + 3 < N) v.w = wp[3];
            }
            Bs[r][c + 0] = v.x; Bs[r][c + 1] = v.y;
            Bs[r][c + 2] = v.z; Bs[r][c + 3] = v.w;
        }
        __syncthreads();

#pragma unroll
        for (int kk = 0; kk < BK; kk++) {
            float4 a0 = *(const float4*)&As[kk][ty * TM];
            float4 a1 = *(const float4*)&As[kk][ty * TM + 4];
            float4 b0 = *(const float4*)&Bs[kk][tx * TN];
            float4 b1 = *(const float4*)&Bs[kk][tx * TN + 4];
            float ar[TM] = {a0.x, a0.y, a0.z, a0.w, a1.x, a1.y, a1.z, a1.w};
            float br[TN] = {b0.x, b0.y, b0.z, b0.w, b1.x, b1.y, b1.z, b1.w};
#pragma unroll
            for (int i = 0; i < TM; i++)
#pragma unroll
                for (int j = 0; j < TN; j++)
                    acc[i][j] += ar[i] * br[j];
        }
        __syncthreads();
    }

    // --- epilogue: bias (+relu) + store ---
#pragma unroll
    for (int i = 0; i < TM; i++) {
        int grow = tileM + ty * TM + i;
        if (grow >= M) continue;
#pragma unroll
        for (int j = 0; j < TN; j++) {
            int gcol = tileN + tx * TN + j;
            if (gcol >= N) continue;
            float v = acc[i][j] + Bias[gcol];
            if (RELU) v = fmaxf(v, 0.f);
            C[(size_t)grow * N + gcol] = v;
        }
    }
}

// ---------------------------------------------------------------------------
// keys normalization: one warp per expert row
// ---------------------------------------------------------------------------
__global__ void keysn_kernel(const float* __restrict__ keys)
{
    int e    = threadIdx.x >> 5;
    int lane = threadIdx.x & 31;
    if (e >= EDIM) return;
    float4 v = *(const float4*)(keys + e * KDIM + lane * 4);
    float ss = v.x * v.x + v.y * v.y + v.z * v.z + v.w * v.w;
#pragma unroll
    for (int o = 16; o; o >>= 1) ss += __shfl_xor_sync(0xffffffffu, ss, o);
    float inv = 1.f / fmaxf(sqrtf(ss), 1e-12f);
    float4 o4 = make_float4(v.x * inv, v.y * inv, v.z * inv, v.w * inv);
    *(float4*)(g_keysn + e * KDIM + lane * 4) = o4;
}

__global__ void zero_counts_kernel()
{
    if (threadIdx.x < EDIM) g_counts[threadIdx.x] = 0;
}

// ---------------------------------------------------------------------------
// Router: warp per token. normalize pk, 8 cosine sims, top-2, softmax.
// ---------------------------------------------------------------------------
__global__ void router_kernel()
{
    int warp = threadIdx.x >> 5;
    int lane = threadIdx.x & 31;
    int t = blockIdx.x * 8 + warp;
    if (t >= BDIM) return;

    float4 v = *(const float4*)(g_pk + (size_t)t * KDIM + lane * 4);
    float ss = v.x * v.x + v.y * v.y + v.z * v.z + v.w * v.w;
#pragma unroll
    for (int o = 16; o; o >>= 1) ss += __shfl_xor_sync(0xffffffffu, ss, o);
    float inv = 1.f / fmaxf(sqrtf(ss), 1e-12f);

    float sims[EDIM];
#pragma unroll
    for (int e = 0; e < EDIM; e++) {
        float4 kv = *(const float4*)(g_keysn + e * KDIM + lane * 4);
        float d = v.x * kv.x + v.y * kv.y + v.z * kv.z + v.w * kv.w;
#pragma unroll
        for (int o = 16; o; o >>= 1) d += __shfl_xor_sync(0xffffffffu, d, o);
        sims[e] = d * inv;
    }

    if (lane == 0) {
        int i0 = 0; float v0 = sims[0];
#pragma unroll
        for (int e = 1; e < EDIM; e++) if (sims[e] > v0) { v0 = sims[e]; i0 = e; }
        int i1 = -1; float v1 = -1e30f;
#pragma unroll
        for (int e = 0; e < EDIM; e++) if (e != i0 && sims[e] > v1) { v1 = sims[e]; i1 = e; }

        float e1 = expf(v1 - v0);
        float s  = 1.f + e1;
        float w0 = 1.f / s;
        float w1 = e1 / s;

#pragma unroll
        for (int e = 0; e < EDIM; e++) {
            g_sim[t * EDIM + e] = sims[e];
            g_weights[t * EDIM + e] = (e == i0) ? w0 : ((e == i1) ? w1 : 0.f);
        }
        g_topi[t * TOPK + 0] = i0;
        g_topi[t * TOPK + 1] = i1;
        g_wslot[t * TOPK + 0] = w0;
        g_wslot[t * TOPK + 1] = w1;
        atomicAdd(&g_counts[i0], 1);
        atomicAdd(&g_counts[i1], 1);
    }
}

__global__ void scan_kernel()
{
    if (threadIdx.x == 0) {
        int off = 0;
        for (int e = 0; e < EDIM; e++) {
            g_offsets[e] = off;
            g_cursor[e]  = off;
            off += g_counts[e];
        }
        g_offsets[EDIM] = off;
    }
}

__global__ void scatter_kernel()
{
    int t = blockIdx.x * blockDim.x + threadIdx.x;
    if (t >= BDIM) return;
#pragma unroll
    for (int s = 0; s < TOPK; s++) {
        int e = g_topi[t * TOPK + s];
        int pos = atomicAdd(&g_cursor[e], 1);
        g_list[pos] = t;
        g_pos[t * TOPK + s] = pos;
    }
}

// ---------------------------------------------------------------------------
// Combine: final[t,c] = w0 * eout[p0,c] + w1 * eout[p1,c]
// ---------------------------------------------------------------------------
__global__ void combine_kernel(float* __restrict__ out)
{
    int t = blockIdx.x;
    float w0 = g_wslot[t * TOPK + 0];
    float w1 = g_wslot[t * TOPK + 1];
    size_t p0 = (size_t)g_pos[t * TOPK + 0];
    size_t p1 = (size_t)g_pos[t * TOPK + 1];
    for (int c = threadIdx.x; c < CDIM; c += blockDim.x)
        out[(size_t)t * CDIM + c] =
            w0 * g_eout[p0 * CDIM + c] + w1 * g_eout[p1 * CDIM + c];
}

// Write secondary outputs (weights, top_i, sim) if the out buffer holds them.
__global__ void tail_writer_kernel(float* __restrict__ out, long long out_size)
{
    long long i = (long long)blockIdx.x * blockDim.x + threadIdx.x;
    const long long base_w = (long long)BDIM * CDIM;
    const long long n_w = BDIM * EDIM;
    const long long base_t = base_w + n_w;
    const long long n_t = BDIM * TOPK;
    const long long base_s = base_t + n_t;
    const long long n_s = BDIM * EDIM;
    if (i < n_w && base_w + i < out_size) out[base_w + i] = g_weights[i];
    if (i < n_t && base_t + i < out_size) out[base_t + i] = (float)g_topi[i];
    if (i < n_s && base_s + i < out_size) out[base_s + i] = g_sim[i];
}

// ---------------------------------------------------------------------------
// Launch
// ---------------------------------------------------------------------------
extern "C" void kernel_launch(void* const* d_in, const int* in_sizes, int n_in,
                              void* d_out, int out_size)
{
    const float* x    = (const float*)d_in[0];
    const float* fw1  = (const float*)d_in[1];
    const float* fb1  = (const float*)d_in[2];
    const float* fw2  = (const float*)d_in[3];
    const float* fb2  = (const float*)d_in[4];
    const float* kw   = (const float*)d_in[5];
    const float* kb   = (const float*)d_in[6];
    const float* keys = (const float*)d_in[7];
    const float* ew1  = (const float*)d_in[8];
    const float* eb1  = (const float*)d_in[9];
    const float* ew2  = (const float*)d_in[10];
    const float* eb2  = (const float*)d_in[11];
    const float* ew3  = (const float*)d_in[12];
    const float* eb3  = (const float*)d_in[13];
    float* out = (float*)d_out;

    dim3 blk(256);

    keysn_kernel<<<1, 256>>>(keys);
    zero_counts_kernel<<<1, 32>>>();

    // feature extractor
    gemm_k<0, true ><<<dim3(HDIM / BN, BDIM / BM), blk>>>(x,       fw1, fb1, BDIM, HDIM, DDIM);
    gemm_k<1, false><<<dim3(HDIM / BN, BDIM / BM), blk>>>(nullptr, fw2, fb2, BDIM, HDIM, HDIM);

    // router projection + routing + grouping
    gemm_k<2, false><<<dim3(1, BDIM / BM), blk>>>(nullptr, kw, kb, BDIM, KDIM, HDIM);
    router_kernel<<<BDIM / 8, 256>>>();
    scan_kernel<<<1, 32>>>();
    scatter_kernel<<<(BDIM + 255) / 256, 256>>>();

    // expert MLPs on grouped (top-2 only) rows
    gemm_k<3, true ><<<dim3(HDIM / BN,  BDIM / BM, EDIM), blk>>>(nullptr, ew1, eb1, 0, HDIM,  HDIM);
    gemm_k<4, true ><<<dim3(H2DIM / BN, BDIM / BM, EDIM), blk>>>(nullptr, ew2, eb2, 0, H2DIM, HDIM);
    gemm_k<5, false><<<dim3((CDIM + BN - 1) / BN, BDIM / BM, EDIM), blk>>>(nullptr, ew3, eb3, 0, CDIM, H2DIM);

    // combine + secondary outputs
    combine_kernel<<<BDIM, 256>>>(out);
    tail_writer_kernel<<<(BDIM * EDIM + 255) / 256, 256>>>(out, (long long)out_size);
}

// round 4
// speedup vs baseline: 1.7040x; 1.7040x over previous
#include <cuda_runtime.h>
#include <cuda_bf16.h>
#include <math.h>
#include <stdint.h>

// ---------------------------------------------------------------------------
// Problem constants
// ---------------------------------------------------------------------------
#define BDIM   8192
#define DDIM   1024
#define HDIM   2048
#define H2DIM  1024
#define CDIM   1000
#define KDIM   128
#define EDIM   8
#define TOPK   2
#define MAXROWS (BDIM * TOPK)   // 16384 grouped rows

// ---------------------------------------------------------------------------
// Scratch (device globals — no allocation allowed)
// ---------------------------------------------------------------------------
__device__ float g_h    [(size_t)BDIM * HDIM];     // relu(x@fw1+fb1)
__device__ float g_feats[(size_t)BDIM * HDIM];     // feats
__device__ float g_pk   [(size_t)BDIM * KDIM];     // feats@kw+kb (pre-norm)
__device__ float g_keysn[EDIM * KDIM];             // normalized keys
__device__ float g_sim  [BDIM * EDIM];
__device__ float g_weights[BDIM * EDIM];
__device__ float g_wslot[BDIM * TOPK];             // softmax weights per slot
__device__ int   g_topi [BDIM * TOPK];
__device__ int   g_counts[EDIM];
__device__ int   g_offsets[EDIM + 1];
__device__ int   g_cursor[EDIM];
__device__ int   g_list [MAXROWS];                 // token ids grouped by expert
__device__ int   g_pos  [BDIM * TOPK];             // grouped row of (token,slot)
__device__ float g_h1   [(size_t)MAXROWS * HDIM];  // 128 MB
__device__ float g_h2   [(size_t)MAXROWS * H2DIM]; // 64 MB
__device__ float g_eout [(size_t)MAXROWS * CDIM];  // 64 MB

// ---------------------------------------------------------------------------
// Tiled fp32 GEMM (router-feeding stages only — must stay fp32-accurate):
// STAGE: 0 x->g_h  1 g_h->g_feats  2 g_feats->g_pk
// ---------------------------------------------------------------------------
#define BM 128
#define BN 128
#define BK 16
#define TM 8
#define TN 8

template<int STAGE, bool RELU>
__global__ __launch_bounds__(256) void gemm_k(const float* __restrict__ Aext,
                                              const float* __restrict__ W,
                                              const float* __restrict__ Bias,
                                              int M, int N, int Kd)
{
    const float* A;
    float* C;

    if (STAGE == 0)      { A = Aext;    C = g_h;     }
    else if (STAGE == 1) { A = g_h;     C = g_feats; }
    else                 { A = g_feats; C = g_pk;    }

    const int tileM = blockIdx.y * BM;
    const int tileN = blockIdx.x * BN;
    if (tileM >= M) return;

    __shared__ float As[BK][BM];
    __shared__ float Bs[BK][BN];

    const int tid = threadIdx.x;
    const int ty  = tid >> 4;   // 0..15
    const int tx  = tid & 15;   // 0..15

    float acc[TM][TN];
#pragma unroll
    for (int i = 0; i < TM; i++)
#pragma unroll
        for (int j = 0; j < TN; j++) acc[i][j] = 0.f;

    for (int k0 = 0; k0 < Kd; k0 += BK) {
        // --- load A tile (BM x BK), store transposed As[k][m] ---
#pragma unroll
        for (int it = 0; it < 2; it++) {
            int r = (tid >> 2) + it * 64;      // 0..127
            int c = (tid & 3) * 4;             // 0..12
            int grow = tileM + r;
            float4 v = make_float4(0.f, 0.f, 0.f, 0.f);
            if (grow < M) {
                v = *(const float4*)(A + (size_t)grow * Kd + k0 + c);
            }
            As[c + 0][r] = v.x; As[c + 1][r] = v.y;
            As[c + 2][r] = v.z; As[c + 3][r] = v.w;
        }
        // --- load W tile (BK x BN) ---
#pragma unroll
        for (int it = 0; it < 2; it++) {
            int r = (tid >> 5) + it * 8;       // 0..15
            int c = (tid & 31) * 4;            // 0..124
            int gcol = tileN + c;
            float4 v = make_float4(0.f, 0.f, 0.f, 0.f);
            const float* wp = W + (size_t)(k0 + r) * N + gcol;
            if (gcol + 3 < N) {
                v = *(const float4*)wp;
            } else {
                if (gcol + 0 < N) v.x = wp[0];
                if (gcol + 1 < N) v.y = wp[1];
                if (gcol + 2 < N) v.z = wp[2];
                if (gcol + 3 < N) v.w = wp[3];
            }
            Bs[r][c + 0] = v.x; Bs[r][c + 1] = v.y;
            Bs[r][c + 2] = v.z; Bs[r][c + 3] = v.w;
        }
        __syncthreads();

#pragma unroll
        for (int kk = 0; kk < BK; kk++) {
            float4 a0 = *(const float4*)&As[kk][ty * TM];
            float4 a1 = *(const float4*)&As[kk][ty * TM + 4];
            float4 b0 = *(const float4*)&Bs[kk][tx * TN];
            float4 b1 = *(const float4*)&Bs[kk][tx * TN + 4];
            float ar[TM] = {a0.x, a0.y, a0.z, a0.w, a1.x, a1.y, a1.z, a1.w};
            float br[TN] = {b0.x, b0.y, b0.z, b0.w, b1.x, b1.y, b1.z, b1.w};
#pragma unroll
            for (int i = 0; i < TM; i++)
#pragma unroll
                for (int j = 0; j < TN; j++)
                    acc[i][j] += ar[i] * br[j];
        }
        __syncthreads();
    }

#pragma unroll
    for (int i = 0; i < TM; i++) {
        int grow = tileM + ty * TM + i;
        if (grow >= M) continue;
#pragma unroll
        for (int j = 0; j < TN; j++) {
            int gcol = tileN + tx * TN + j;
            if (gcol >= N) continue;
            float v = acc[i][j] + Bias[gcol];
            if (RELU) v = fmaxf(v, 0.f);
            C[(size_t)grow * N + gcol] = v;
        }
    }
}

// ---------------------------------------------------------------------------
// TF32 tensor-core GEMM for the expert stages (3,4,5).
//   C = act(A[M,Kd] @ W_e[Kd,N] + bias_e)   with M = rows grouped to expert e.
// Tile 128x128x32, 8 warps, warp tile 64x32 via mma.sync.m16n8k8 tf32.
// Operands rounded fp32->tf32 with cvt.rna (unbiased) at SMEM store time.
// ---------------------------------------------------------------------------
#define TBK 32

__device__ __forceinline__ float cvt_tf32(float x) {
    float r;
    asm("cvt.rna.tf32.f32 %0, %1;" : "=f"(r) : "f"(x));
    return r;
}

__device__ __forceinline__ void mma_tf32(float c[4],
                                         const uint32_t a[4],
                                         const uint32_t b[2]) {
    asm volatile(
        "mma.sync.aligned.m16n8k8.row.col.f32.tf32.tf32.f32 "
        "{%0,%1,%2,%3}, {%4,%5,%6,%7}, {%8,%9}, {%0,%1,%2,%3};"
        : "+f"(c[0]), "+f"(c[1]), "+f"(c[2]), "+f"(c[3])
        : "r"(a[0]), "r"(a[1]), "r"(a[2]), "r"(a[3]),
          "r"(b[0]), "r"(b[1]));
}

template<int STAGE, bool RELU>
__global__ __launch_bounds__(256) void tgemm_k(const float* __restrict__ Wg,
                                               const float* __restrict__ Biasg,
                                               int N, int Kd)
{
    const int e  = blockIdx.z;
    const int m0 = g_offsets[e];
    const int M  = g_offsets[e + 1] - m0;

    const int tileM = blockIdx.y * 128;
    if (tileM >= M) return;
    const int tileN = blockIdx.x * 128;

    const float* W    = Wg    + (size_t)e * Kd * N;
    const float* Bias = Biasg + (size_t)e * N;

    const float* A;
    float* C;
    const int* gather = nullptr;
    if (STAGE == 3)      { A = g_feats; gather = g_list + m0; C = g_h1   + (size_t)m0 * N; }
    else if (STAGE == 4) { A = g_h1  + (size_t)m0 * Kd;       C = g_h2   + (size_t)m0 * N; }
    else                 { A = g_h2  + (size_t)m0 * Kd;       C = g_eout + (size_t)m0 * N; }

    // A: [128 rows][32 k] stride 36  -> frag loads bank-free (4g+tig)
    // B: [32 k][128 n]   stride 136 -> frag loads bank-free (8tig+g)
    __shared__ float As[128][36];
    __shared__ float Bs[TBK][136];

    const int tid  = threadIdx.x;
    const int lane = tid & 31;
    const int wid  = tid >> 5;
    const int g    = lane >> 2;
    const int tig  = lane & 3;
    const int warpM = wid & 1;   // 2 warps along M (2*64 = 128)
    const int warpN = wid >> 1;  // 4 warps along N (4*32 = 128)

    float acc[4][4][4];
#pragma unroll
    for (int i = 0; i < 4; i++)
#pragma unroll
        for (int j = 0; j < 4; j++)
#pragma unroll
            for (int r = 0; r < 4; r++) acc[i][j][r] = 0.f;

    for (int k0 = 0; k0 < Kd; k0 += TBK) {
        // --- load A tile (128 x 32): 4 float4 per thread, K always in-bounds ---
#pragma unroll
        for (int it = 0; it < 4; it++) {
            int r = (tid >> 3) + it * 32;     // 0..127
            int c = (tid & 7) * 4;            // 0..28
            int grow = tileM + r;
            float4 v = make_float4(0.f, 0.f, 0.f, 0.f);
            if (grow < M) {
                size_t arow = (STAGE == 3) ? (size_t)gather[grow] : (size_t)grow;
                v = *(const float4*)(A + arow * Kd + k0 + c);
            }
            As[r][c + 0] = cvt_tf32(v.x);
            As[r][c + 1] = cvt_tf32(v.y);
            As[r][c + 2] = cvt_tf32(v.z);
            As[r][c + 3] = cvt_tf32(v.w);
        }
        // --- load B tile (32 x 128) ---
#pragma unroll
        for (int it = 0; it < 4; it++) {
            int r = (tid >> 5) + it * 8;      // 0..31
            int c = (tid & 31) * 4;           // 0..124
            int gcol = tileN + c;
            float4 v = make_float4(0.f, 0.f, 0.f, 0.f);
            const float* wp = W + (size_t)(k0 + r) * N + gcol;
            if (gcol + 3 < N) {
                v = *(const float4*)wp;
            } else {
                if (gcol + 0 < N) v.x = wp[0];
                if (gcol + 1 < N) v.y = wp[1];
                if (gcol + 2 < N) v.z = wp[2];
                if (gcol + 3 < N) v.w = wp[3];
            }
            Bs[r][c + 0] = cvt_tf32(v.x);
            Bs[r][c + 1] = cvt_tf32(v.y);
            Bs[r][c + 2] = cvt_tf32(v.z);
            Bs[r][c + 3] = cvt_tf32(v.w);
        }
        __syncthreads();

#pragma unroll
        for (int ks = 0; ks < 4; ks++) {
            const int k8 = ks * 8;
            uint32_t af[4][4], bf[4][2];
#pragma unroll
            for (int mf = 0; mf < 4; mf++) {
                int m = warpM * 64 + mf * 16 + g;
                af[mf][0] = __float_as_uint(As[m    ][k8 + tig    ]);
                af[mf][1] = __float_as_uint(As[m + 8][k8 + tig    ]);
                af[mf][2] = __float_as_uint(As[m    ][k8 + tig + 4]);
                af[mf][3] = __float_as_uint(As[m + 8][k8 + tig + 4]);
            }
#pragma unroll
            for (int nf = 0; nf < 4; nf++) {
                int n = warpN * 32 + nf * 8 + g;
                bf[nf][0] = __float_as_uint(Bs[k8 + tig    ][n]);
                bf[nf][1] = __float_as_uint(Bs[k8 + tig + 4][n]);
            }
#pragma unroll
            for (int mf = 0; mf < 4; mf++)
#pragma unroll
                for (int nf = 0; nf < 4; nf++)
                    mma_tf32(acc[mf][nf], af[mf], bf[nf]);
        }
        __syncthreads();
    }

    // --- epilogue: bias (+relu) + store ---
#pragma unroll
    for (int mf = 0; mf < 4; mf++) {
        int row0 = tileM + warpM * 64 + mf * 16 + g;
        int row1 = row0 + 8;
#pragma unroll
        for (int nf = 0; nf < 4; nf++) {
            int col0 = tileN + warpN * 32 + nf * 8 + tig * 2;
            int col1 = col0 + 1;
            float b0 = (col0 < N) ? Bias[col0] : 0.f;
            float b1 = (col1 < N) ? Bias[col1] : 0.f;
            float v00 = acc[mf][nf][0] + b0;
            float v01 = acc[mf][nf][1] + b1;
            float v10 = acc[mf][nf][2] + b0;
            float v11 = acc[mf][nf][3] + b1;
            if (RELU) {
                v00 = fmaxf(v00, 0.f); v01 = fmaxf(v01, 0.f);
                v10 = fmaxf(v10, 0.f); v11 = fmaxf(v11, 0.f);
            }
            if (row0 < M) {
                if (col0 < N) C[(size_t)row0 * N + col0] = v00;
                if (col1 < N) C[(size_t)row0 * N + col1] = v01;
            }
            if (row1 < M) {
                if (col0 < N) C[(size_t)row1 * N + col0] = v10;
                if (col1 < N) C[(size_t)row1 * N + col1] = v11;
            }
        }
    }
}

// ---------------------------------------------------------------------------
// keys normalization: one warp per expert row
// ---------------------------------------------------------------------------
__global__ void keysn_kernel(const float* __restrict__ keys)
{
    int e    = threadIdx.x >> 5;
    int lane = threadIdx.x & 31;
    if (e >= EDIM) return;
    float4 v = *(const float4*)(keys + e * KDIM + lane * 4);
    float ss = v.x * v.x + v.y * v.y + v.z * v.z + v.w * v.w;
#pragma unroll
    for (int o = 16; o; o >>= 1) ss += __shfl_xor_sync(0xffffffffu, ss, o);
    float inv = 1.f / fmaxf(sqrtf(ss), 1e-12f);
    float4 o4 = make_float4(v.x * inv, v.y * inv, v.z * inv, v.w * inv);
    *(float4*)(g_keysn + e * KDIM + lane * 4) = o4;
}

__global__ void zero_counts_kernel()
{
    if (threadIdx.x < EDIM) g_counts[threadIdx.x] = 0;
}

// ---------------------------------------------------------------------------
// Router: warp per token. normalize pk, 8 cosine sims, top-2, softmax.
// ---------------------------------------------------------------------------
__global__ void router_kernel()
{
    int warp = threadIdx.x >> 5;
    int lane = threadIdx.x & 31;
    int t = blockIdx.x * 8 + warp;
    if (t >= BDIM) return;

    float4 v = *(const float4*)(g_pk + (size_t)t * KDIM + lane * 4);
    float ss = v.x * v.x + v.y * v.y + v.z * v.z + v.w * v.w;
#pragma unroll
    for (int o = 16; o; o >>= 1) ss += __shfl_xor_sync(0xffffffffu, ss, o);
    float inv = 1.f / fmaxf(sqrtf(ss), 1e-12f);

    float sims[EDIM];
#pragma unroll
    for (int e = 0; e < EDIM; e++) {
        float4 kv = *(const float4*)(g_keysn + e * KDIM + lane * 4);
        float d = v.x * kv.x + v.y * kv.y + v.z * kv.z + v.w * kv.w;
#pragma unroll
        for (int o = 16; o; o >>= 1) d += __shfl_xor_sync(0xffffffffu, d, o);
        sims[e] = d * inv;
    }

    if (lane == 0) {
        int i0 = 0; float v0 = sims[0];
#pragma unroll
        for (int e = 1; e < EDIM; e++) if (sims[e] > v0) { v0 = sims[e]; i0 = e; }
        int i1 = -1; float v1 = -1e30f;
#pragma unroll
        for (int e = 0; e < EDIM; e++) if (e != i0 && sims[e] > v1) { v1 = sims[e]; i1 = e; }

        float e1 = expf(v1 - v0);
        float s  = 1.f + e1;
        float w0 = 1.f / s;
        float w1 = e1 / s;

#pragma unroll
        for (int e = 0; e < EDIM; e++) {
            g_sim[t * EDIM + e] = sims[e];
            g_weights[t * EDIM + e] = (e == i0) ? w0 : ((e == i1) ? w1 : 0.f);
        }
        g_topi[t * TOPK + 0] = i0;
        g_topi[t * TOPK + 1] = i1;
        g_wslot[t * TOPK + 0] = w0;
        g_wslot[t * TOPK + 1] = w1;
        atomicAdd(&g_counts[i0], 1);
        atomicAdd(&g_counts[i1], 1);
    }
}

__global__ void scan_kernel()
{
    if (threadIdx.x == 0) {
        int off = 0;
        for (int e = 0; e < EDIM; e++) {
            g_offsets[e] = off;
            g_cursor[e]  = off;
            off += g_counts[e];
        }
        g_offsets[EDIM] = off;
    }
}

__global__ void scatter_kernel()
{
    int t = blockIdx.x * blockDim.x + threadIdx.x;
    if (t >= BDIM) return;
#pragma unroll
    for (int s = 0; s < TOPK; s++) {
        int e = g_topi[t * TOPK + s];
        int pos = atomicAdd(&g_cursor[e], 1);
        g_list[pos] = t;
        g_pos[t * TOPK + s] = pos;
    }
}

// ---------------------------------------------------------------------------
// Combine: final[t,c] = w0 * eout[p0,c] + w1 * eout[p1,c]
// ---------------------------------------------------------------------------
__global__ void combine_kernel(float* __restrict__ out)
{
    int t = blockIdx.x;
    float w0 = g_wslot[t * TOPK + 0];
    float w1 = g_wslot[t * TOPK + 1];
    size_t p0 = (size_t)g_pos[t * TOPK + 0];
    size_t p1 = (size_t)g_pos[t * TOPK + 1];
    for (int c = threadIdx.x; c < CDIM; c += blockDim.x)
        out[(size_t)t * CDIM + c] =
            w0 * g_eout[p0 * CDIM + c] + w1 * g_eout[p1 * CDIM + c];
}

// Write secondary outputs (weights, top_i, sim) if the out buffer holds them.
__global__ void tail_writer_kernel(float* __restrict__ out, long long out_size)
{
    long long i = (long long)blockIdx.x * blockDim.x + threadIdx.x;
    const long long base_w = (long long)BDIM * CDIM;
    const long long n_w = BDIM * EDIM;
    const long long base_t = base_w + n_w;
    const long long n_t = BDIM * TOPK;
    const long long base_s = base_t + n_t;
    const long long n_s = BDIM * EDIM;
    if (i < n_w && base_w + i < out_size) out[base_w + i] = g_weights[i];
    if (i < n_t && base_t + i < out_size) out[base_t + i] = (float)g_topi[i];
    if (i < n_s && base_s + i < out_size) out[base_s + i] = g_sim[i];
}

// ---------------------------------------------------------------------------
// Launch
// ---------------------------------------------------------------------------
extern "C" void kernel_launch(void* const* d_in, const int* in_sizes, int n_in,
                              void* d_out, int out_size)
{
    const float* x    = (const float*)d_in[0];
    const float* fw1  = (const float*)d_in[1];
    const float* fb1  = (const float*)d_in[2];
    const float* fw2  = (const float*)d_in[3];
    const float* fb2  = (const float*)d_in[4];
    const float* kw   = (const float*)d_in[5];
    const float* kb   = (const float*)d_in[6];
    const float* keys = (const float*)d_in[7];
    const float* ew1  = (const float*)d_in[8];
    const float* eb1  = (const float*)d_in[9];
    const float* ew2  = (const float*)d_in[10];
    const float* eb2  = (const float*)d_in[11];
    const float* ew3  = (const float*)d_in[12];
    const float* eb3  = (const float*)d_in[13];
    float* out = (float*)d_out;

    dim3 blk(256);

    keysn_kernel<<<1, 256>>>(keys);
    zero_counts_kernel<<<1, 32>>>();

    // feature extractor + router projection: fp32 (routing must be exact)
    gemm_k<0, true ><<<dim3(HDIM / BN, BDIM / BM), blk>>>(x,       fw1, fb1, BDIM, HDIM, DDIM);
    gemm_k<1, false><<<dim3(HDIM / BN, BDIM / BM), blk>>>(nullptr, fw2, fb2, BDIM, HDIM, HDIM);
    gemm_k<2, false><<<dim3(1, BDIM / BM), blk>>>(nullptr, kw, kb, BDIM, KDIM, HDIM);

    router_kernel<<<BDIM / 8, 256>>>();
    scan_kernel<<<1, 32>>>();
    scatter_kernel<<<(BDIM + 255) / 256, 256>>>();

    // expert MLPs: TF32 tensor cores on grouped (top-2 only) rows
    tgemm_k<3, true ><<<dim3(HDIM / 128,  BDIM / 128, EDIM), blk>>>(ew1, eb1, HDIM,  HDIM);
    tgemm_k<4, true ><<<dim3(H2DIM / 128, BDIM / 128, EDIM), blk>>>(ew2, eb2, H2DIM, HDIM);
    tgemm_k<5, false><<<dim3((CDIM + 127) / 128, BDIM / 128, EDIM), blk>>>(ew3, eb3, CDIM, H2DIM);

    // combine + secondary outputs
    combine_kernel<<<BDIM, 256>>>(out);
    tail_writer_kernel<<<(BDIM * EDIM + 255) / 256, 256>>>(out, (long long)out_size);
}

// round 5
// speedup vs baseline: 2.4763x; 1.4532x over previous
#include <cuda_runtime.h>
#include <cuda_bf16.h>
#include <math.h>
#include <stdint.h>

// ---------------------------------------------------------------------------
// Problem constants
// ---------------------------------------------------------------------------
#define BDIM   8192
#define DDIM   1024
#define HDIM   2048
#define H2DIM  1024
#define CDIM   1000
#define KDIM   128
#define EDIM   8
#define TOPK   2
#define MAXROWS (BDIM * TOPK)   // 16384 grouped rows

// ---------------------------------------------------------------------------
// Scratch (device globals — no allocation allowed)
// ---------------------------------------------------------------------------
__device__ float g_h    [(size_t)BDIM * HDIM];
__device__ float g_feats[(size_t)BDIM * HDIM];
__device__ float g_pk   [(size_t)BDIM * KDIM];
__device__ float g_keysn[EDIM * KDIM];
__device__ float g_sim  [BDIM * EDIM];
__device__ float g_weights[BDIM * EDIM];
__device__ float g_wslot[BDIM * TOPK];
__device__ int   g_topi [BDIM * TOPK];
__device__ int   g_counts[EDIM];
__device__ int   g_offsets[EDIM + 1];
__device__ int   g_cursor[EDIM];
__device__ int   g_list [MAXROWS];
__device__ int   g_pos  [BDIM * TOPK];
__device__ float g_h1   [(size_t)MAXROWS * HDIM];
__device__ float g_h2   [(size_t)MAXROWS * H2DIM];
__device__ float g_eout [(size_t)MAXROWS * CDIM];

// ---------------------------------------------------------------------------
// fp32 GEMM (kept only for stage 2: g_feats -> g_pk, small)
// ---------------------------------------------------------------------------
#define BM 128
#define BN 128
#define BK 16
#define TM 8
#define TN 8

template<int STAGE, bool RELU>
__global__ __launch_bounds__(256) void gemm_k(const float* __restrict__ Aext,
                                              const float* __restrict__ W,
                                              const float* __restrict__ Bias,
                                              int M, int N, int Kd)
{
    const float* A = g_feats;
    float* C = g_pk;

    const int tileM = blockIdx.y * BM;
    const int tileN = blockIdx.x * BN;
    if (tileM >= M) return;

    __shared__ float As[BK][BM];
    __shared__ float Bs[BK][BN];

    const int tid = threadIdx.x;
    const int ty  = tid >> 4;
    const int tx  = tid & 15;

    float acc[TM][TN];
#pragma unroll
    for (int i = 0; i < TM; i++)
#pragma unroll
        for (int j = 0; j < TN; j++) acc[i][j] = 0.f;

    for (int k0 = 0; k0 < Kd; k0 += BK) {
#pragma unroll
        for (int it = 0; it < 2; it++) {
            int r = (tid >> 2) + it * 64;
            int c = (tid & 3) * 4;
            int grow = tileM + r;
            float4 v = make_float4(0.f, 0.f, 0.f, 0.f);
            if (grow < M) v = *(const float4*)(A + (size_t)grow * Kd + k0 + c);
            As[c + 0][r] = v.x; As[c + 1][r] = v.y;
            As[c + 2][r] = v.z; As[c + 3][r] = v.w;
        }
#pragma unroll
        for (int it = 0; it < 2; it++) {
            int r = (tid >> 5) + it * 8;
            int c = (tid & 31) * 4;
            int gcol = tileN + c;
            float4 v = make_float4(0.f, 0.f, 0.f, 0.f);
            const float* wp = W + (size_t)(k0 + r) * N + gcol;
            if (gcol + 3 < N) v = *(const float4*)wp;
            else {
                if (gcol + 0 < N) v.x = wp[0];
                if (gcol + 1 < N) v.y = wp[1];
                if (gcol + 2 < N) v.z = wp[2];
                if (gcol + 3 < N) v.w = wp[3];
            }
            Bs[r][c + 0] = v.x; Bs[r][c + 1] = v.y;
            Bs[r][c + 2] = v.z; Bs[r][c + 3] = v.w;
        }
        __syncthreads();

#pragma unroll
        for (int kk = 0; kk < BK; kk++) {
            float4 a0 = *(const float4*)&As[kk][ty * TM];
            float4 a1 = *(const float4*)&As[kk][ty * TM + 4];
            float4 b0 = *(const float4*)&Bs[kk][tx * TN];
            float4 b1 = *(const float4*)&Bs[kk][tx * TN + 4];
            float ar[TM] = {a0.x, a0.y, a0.z, a0.w, a1.x, a1.y, a1.z, a1.w};
            float br[TN] = {b0.x, b0.y, b0.z, b0.w, b1.x, b1.y, b1.z, b1.w};
#pragma unroll
            for (int i = 0; i < TM; i++)
#pragma unroll
                for (int j = 0; j < TN; j++)
                    acc[i][j] += ar[i] * br[j];
        }
        __syncthreads();
    }

#pragma unroll
    for (int i = 0; i < TM; i++) {
        int grow = tileM + ty * TM + i;
        if (grow >= M) continue;
#pragma unroll
        for (int j = 0; j < TN; j++) {
            int gcol = tileN + tx * TN + j;
            if (gcol >= N) continue;
            float v = acc[i][j] + Bias[gcol];
            if (RELU) v = fmaxf(v, 0.f);
            C[(size_t)grow * N + gcol] = v;
        }
    }
}

// ---------------------------------------------------------------------------
// TF32 tensor-core GEMM, cp.async double-buffered, raw fp32 in SMEM,
// tf32 cvt (SPLIT=1) or hi/lo 3xTF32 split (SPLIT=3) applied in registers.
//   STAGE 0: x       @ fw1 -> g_h      (SPLIT=3, relu)
//   STAGE 1: g_h     @ fw2 -> g_feats  (SPLIT=3)
//   STAGE 3: gather(g_feats) @ ew1[e] -> g_h1   (SPLIT=1, relu)
//   STAGE 4: g_h1    @ ew2[e] -> g_h2  (SPLIT=1, relu)
//   STAGE 5: g_h2    @ ew3[e] -> g_eout(SPLIT=1)
// Tile 128x128x32, 8 warps (warp tile 64x32), mma.sync.m16n8k8 tf32.
// ---------------------------------------------------------------------------
#define TBK 32

__device__ __forceinline__ float cvt_tf32(float x) {
    float r;
    asm("cvt.rna.tf32.f32 %0, %1;" : "=f"(r) : "f"(x));
    return r;
}

__device__ __forceinline__ void mma_tf32(float c[4],
                                         const uint32_t a[4],
                                         const uint32_t b[2]) {
    asm volatile(
        "mma.sync.aligned.m16n8k8.row.col.f32.tf32.tf32.f32 "
        "{%0,%1,%2,%3}, {%4,%5,%6,%7}, {%8,%9}, {%0,%1,%2,%3};"
        : "+f"(c[0]), "+f"(c[1]), "+f"(c[2]), "+f"(c[3])
        : "r"(a[0]), "r"(a[1]), "r"(a[2]), "r"(a[3]),
          "r"(b[0]), "r"(b[1]));
}

__device__ __forceinline__ void cp16(void* dst, const void* src, bool valid) {
    uint32_t d = (uint32_t)__cvta_generic_to_shared(dst);
    int sz = valid ? 16 : 0;
    asm volatile("cp.async.cg.shared.global [%0], [%1], 16, %2;"
                 :: "r"(d), "l"(src), "r"(sz));
}
__device__ __forceinline__ void cp_commit() {
    asm volatile("cp.async.commit_group;");
}

template<int STAGE, bool RELU, int SPLIT>
__global__ __launch_bounds__(256) void tgemm_k(const float* __restrict__ Aext,
                                               const float* __restrict__ Wg,
                                               const float* __restrict__ Biasg,
                                               int Mfull, int N, int Kd)
{
    extern __shared__ float sm[];
    float (*As)[128][36] = (float(*)[128][36])sm;                    // 2 x 18432B
    float (*Bs)[TBK][136] = (float(*)[TBK][136])(sm + 2 * 128 * 36); // 2 x 17408B

    int M;
    const float* A;
    const float* W;
    const float* Bias;
    float* C;
    const int* gather = nullptr;

    if (STAGE == 0)      { A = Aext; C = g_h;     M = Mfull; W = Wg; Bias = Biasg; }
    else if (STAGE == 1) { A = g_h;  C = g_feats; M = Mfull; W = Wg; Bias = Biasg; }
    else {
        int e  = blockIdx.z;
        int m0 = g_offsets[e];
        M = g_offsets[e + 1] - m0;
        W    = Wg    + (size_t)e * Kd * N;
        Bias = Biasg + (size_t)e * N;
        if (STAGE == 3)      { A = g_feats; gather = g_list + m0; C = g_h1   + (size_t)m0 * N; }
        else if (STAGE == 4) { A = g_h1  + (size_t)m0 * Kd;       C = g_h2   + (size_t)m0 * N; }
        else                 { A = g_h2  + (size_t)m0 * Kd;       C = g_eout + (size_t)m0 * N; }
    }

    const int tileM = blockIdx.y * 128;
    if (tileM >= M) return;
    const int tileN = blockIdx.x * 128;

    const int tid  = threadIdx.x;
    const int lane = tid & 31;
    const int wid  = tid >> 5;
    const int g    = lane >> 2;
    const int tig  = lane & 3;
    const int warpM = wid & 1;
    const int warpN = wid >> 1;

    // Precompute A row pointers / validity (rows fixed across k-iters)
    const float* aptr[4];
    bool av[4];
#pragma unroll
    for (int it = 0; it < 4; it++) {
        int r = (tid >> 3) + it * 32;
        int grow = tileM + r;
        bool v = (grow < M);
        size_t arow = 0;
        if (v) arow = (STAGE == 3) ? (size_t)gather[grow] : (size_t)grow;
        aptr[it] = A + arow * Kd + (tid & 7) * 4;
        av[it] = v;
    }
    // B column validity (N % 4 == 0, so a float4 is fully in or out)
    const int bc = (tid & 31) * 4;
    const bool bv = (tileN + bc) < N;
    const int br = tid >> 5;

    float acc[4][4][4];
#pragma unroll
    for (int i = 0; i < 4; i++)
#pragma unroll
        for (int j = 0; j < 4; j++)
#pragma unroll
            for (int r = 0; r < 4; r++) acc[i][j][r] = 0.f;

    const int KT = Kd / TBK;

    // ---- async tile loader ----
    auto load_tile = [&](int k0, int buf) {
#pragma unroll
        for (int it = 0; it < 4; it++) {
            int r = (tid >> 3) + it * 32;
            cp16(&As[buf][r][(tid & 7) * 4], aptr[it] + k0, av[it]);
        }
#pragma unroll
        for (int it = 0; it < 4; it++) {
            int r = br + it * 8;
            const float* src = W + (size_t)(k0 + r) * N + tileN + bc;
            cp16(&Bs[buf][r][bc], src, bv);
        }
        cp_commit();
    };

    load_tile(0, 0);

    for (int kt = 0; kt < KT; kt++) {
        const int buf = kt & 1;
        if (kt + 1 < KT) {
            load_tile((kt + 1) * TBK, (kt + 1) & 1);
            asm volatile("cp.async.wait_group 1;");
        } else {
            asm volatile("cp.async.wait_group 0;");
        }
        __syncthreads();

#pragma unroll
        for (int ks = 0; ks < 4; ks++) {
            const int k8 = ks * 8;

            // B fragments for this warp (raw fp32 from SMEM)
            float bfv[4][2];
#pragma unroll
            for (int nf = 0; nf < 4; nf++) {
                int n = warpN * 32 + nf * 8 + g;
                bfv[nf][0] = Bs[buf][k8 + tig    ][n];
                bfv[nf][1] = Bs[buf][k8 + tig + 4][n];
            }

            if (SPLIT == 1) {
                uint32_t bh[4][2];
#pragma unroll
                for (int nf = 0; nf < 4; nf++) {
                    bh[nf][0] = __float_as_uint(cvt_tf32(bfv[nf][0]));
                    bh[nf][1] = __float_as_uint(cvt_tf32(bfv[nf][1]));
                }
#pragma unroll
                for (int mf = 0; mf < 4; mf++) {
                    int m = warpM * 64 + mf * 16 + g;
                    uint32_t ah[4];
                    ah[0] = __float_as_uint(cvt_tf32(As[buf][m    ][k8 + tig    ]));
                    ah[1] = __float_as_uint(cvt_tf32(As[buf][m + 8][k8 + tig    ]));
                    ah[2] = __float_as_uint(cvt_tf32(As[buf][m    ][k8 + tig + 4]));
                    ah[3] = __float_as_uint(cvt_tf32(As[buf][m + 8][k8 + tig + 4]));
#pragma unroll
                    for (int nf = 0; nf < 4; nf++)
                        mma_tf32(acc[mf][nf], ah, bh[nf]);
                }
            } else {
                // 3xTF32 split: C += Ahi*Bhi + Ahi*Blo + Alo*Bhi
                uint32_t bh[4][2], bl[4][2];
#pragma unroll
                for (int nf = 0; nf < 4; nf++) {
#pragma unroll
                    for (int r2 = 0; r2 < 2; r2++) {
                        float b  = bfv[nf][r2];
                        float hi = cvt_tf32(b);
                        float lo = cvt_tf32(b - hi);
                        bh[nf][r2] = __float_as_uint(hi);
                        bl[nf][r2] = __float_as_uint(lo);
                    }
                }
#pragma unroll
                for (int mf = 0; mf < 4; mf++) {
                    int m = warpM * 64 + mf * 16 + g;
                    float afv[4];
                    afv[0] = As[buf][m    ][k8 + tig    ];
                    afv[1] = As[buf][m + 8][k8 + tig    ];
                    afv[2] = As[buf][m    ][k8 + tig + 4];
                    afv[3] = As[buf][m + 8][k8 + tig + 4];
                    uint32_t ah[4], al[4];
#pragma unroll
                    for (int r4 = 0; r4 < 4; r4++) {
                        float hi = cvt_tf32(afv[r4]);
                        float lo = cvt_tf32(afv[r4] - hi);
                        ah[r4] = __float_as_uint(hi);
                        al[r4] = __float_as_uint(lo);
                    }
#pragma unroll
                    for (int nf = 0; nf < 4; nf++) {
                        mma_tf32(acc[mf][nf], al, bh[nf]);
                        mma_tf32(acc[mf][nf], ah, bl[nf]);
                        mma_tf32(acc[mf][nf], ah, bh[nf]);
                    }
                }
            }
        }
        __syncthreads();
    }

    // --- epilogue: bias (+relu) + store ---
#pragma unroll
    for (int mf = 0; mf < 4; mf++) {
        int row0 = tileM + warpM * 64 + mf * 16 + g;
        int row1 = row0 + 8;
#pragma unroll
        for (int nf = 0; nf < 4; nf++) {
            int col0 = tileN + warpN * 32 + nf * 8 + tig * 2;
            int col1 = col0 + 1;
            float b0 = (col0 < N) ? Bias[col0] : 0.f;
            float b1 = (col1 < N) ? Bias[col1] : 0.f;
            float v00 = acc[mf][nf][0] + b0;
            float v01 = acc[mf][nf][1] + b1;
            float v10 = acc[mf][nf][2] + b0;
            float v11 = acc[mf][nf][3] + b1;
            if (RELU) {
                v00 = fmaxf(v00, 0.f); v01 = fmaxf(v01, 0.f);
                v10 = fmaxf(v10, 0.f); v11 = fmaxf(v11, 0.f);
            }
            if (row0 < M) {
                if (col0 < N) C[(size_t)row0 * N + col0] = v00;
                if (col1 < N) C[(size_t)row0 * N + col1] = v01;
            }
            if (row1 < M) {
                if (col0 < N) C[(size_t)row1 * N + col0] = v10;
                if (col1 < N) C[(size_t)row1 * N + col1] = v11;
            }
        }
    }
}

// ---------------------------------------------------------------------------
// keys normalization / routing / grouping / combine (unchanged)
// ---------------------------------------------------------------------------
__global__ void keysn_kernel(const float* __restrict__ keys)
{
    int e    = threadIdx.x >> 5;
    int lane = threadIdx.x & 31;
    if (e >= EDIM) return;
    float4 v = *(const float4*)(keys + e * KDIM + lane * 4);
    float ss = v.x * v.x + v.y * v.y + v.z * v.z + v.w * v.w;
#pragma unroll
    for (int o = 16; o; o >>= 1) ss += __shfl_xor_sync(0xffffffffu, ss, o);
    float inv = 1.f / fmaxf(sqrtf(ss), 1e-12f);
    float4 o4 = make_float4(v.x * inv, v.y * inv, v.z * inv, v.w * inv);
    *(float4*)(g_keysn + e * KDIM + lane * 4) = o4;
}

__global__ void zero_counts_kernel()
{
    if (threadIdx.x < EDIM) g_counts[threadIdx.x] = 0;
}

__global__ void router_kernel()
{
    int warp = threadIdx.x >> 5;
    int lane = threadIdx.x & 31;
    int t = blockIdx.x * 8 + warp;
    if (t >= BDIM) return;

    float4 v = *(const float4*)(g_pk + (size_t)t * KDIM + lane * 4);
    float ss = v.x * v.x + v.y * v.y + v.z * v.z + v.w * v.w;
#pragma unroll
    for (int o = 16; o; o >>= 1) ss += __shfl_xor_sync(0xffffffffu, ss, o);
    float inv = 1.f / fmaxf(sqrtf(ss), 1e-12f);

    float sims[EDIM];
#pragma unroll
    for (int e = 0; e < EDIM; e++) {
        float4 kv = *(const float4*)(g_keysn + e * KDIM + lane * 4);
        float d = v.x * kv.x + v.y * kv.y + v.z * kv.z + v.w * kv.w;
#pragma unroll
        for (int o = 16; o; o >>= 1) d += __shfl_xor_sync(0xffffffffu, d, o);
        sims[e] = d * inv;
    }

    if (lane == 0) {
        int i0 = 0; float v0 = sims[0];
#pragma unroll
        for (int e = 1; e < EDIM; e++) if (sims[e] > v0) { v0 = sims[e]; i0 = e; }
        int i1 = -1; float v1 = -1e30f;
#pragma unroll
        for (int e = 0; e < EDIM; e++) if (e != i0 && sims[e] > v1) { v1 = sims[e]; i1 = e; }

        float e1 = expf(v1 - v0);
        float s  = 1.f + e1;
        float w0 = 1.f / s;
        float w1 = e1 / s;

#pragma unroll
        for (int e = 0; e < EDIM; e++) {
            g_sim[t * EDIM + e] = sims[e];
            g_weights[t * EDIM + e] = (e == i0) ? w0 : ((e == i1) ? w1 : 0.f);
        }
        g_topi[t * TOPK + 0] = i0;
        g_topi[t * TOPK + 1] = i1;
        g_wslot[t * TOPK + 0] = w0;
        g_wslot[t * TOPK + 1] = w1;
        atomicAdd(&g_counts[i0], 1);
        atomicAdd(&g_counts[i1], 1);
    }
}

__global__ void scan_kernel()
{
    if (threadIdx.x == 0) {
        int off = 0;
        for (int e = 0; e < EDIM; e++) {
            g_offsets[e] = off;
            g_cursor[e]  = off;
            off += g_counts[e];
        }
        g_offsets[EDIM] = off;
    }
}

__global__ void scatter_kernel()
{
    int t = blockIdx.x * blockDim.x + threadIdx.x;
    if (t >= BDIM) return;
#pragma unroll
    for (int s = 0; s < TOPK; s++) {
        int e = g_topi[t * TOPK + s];
        int pos = atomicAdd(&g_cursor[e], 1);
        g_list[pos] = t;
        g_pos[t * TOPK + s] = pos;
    }
}

__global__ void combine_kernel(float* __restrict__ out)
{
    int t = blockIdx.x;
    float w0 = g_wslot[t * TOPK + 0];
    float w1 = g_wslot[t * TOPK + 1];
    size_t p0 = (size_t)g_pos[t * TOPK + 0];
    size_t p1 = (size_t)g_pos[t * TOPK + 1];
    for (int c = threadIdx.x; c < CDIM; c += blockDim.x)
        out[(size_t)t * CDIM + c] =
            w0 * g_eout[p0 * CDIM + c] + w1 * g_eout[p1 * CDIM + c];
}

__global__ void tail_writer_kernel(float* __restrict__ out, long long out_size)
{
    long long i = (long long)blockIdx.x * blockDim.x + threadIdx.x;
    const long long base_w = (long long)BDIM * CDIM;
    const long long n_w = BDIM * EDIM;
    const long long base_t = base_w + n_w;
    const long long n_t = BDIM * TOPK;
    const long long base_s = base_t + n_t;
    const long long n_s = BDIM * EDIM;
    if (i < n_w && base_w + i < out_size) out[base_w + i] = g_weights[i];
    if (i < n_t && base_t + i < out_size) out[base_t + i] = (float)g_topi[i];
    if (i < n_s && base_s + i < out_size) out[base_s + i] = g_sim[i];
}

// ---------------------------------------------------------------------------
// Launch
// ---------------------------------------------------------------------------
#define TG_SMEM (2 * (128 * 36 + TBK * 136) * (int)sizeof(float))  // 71680 B

extern "C" void kernel_launch(void* const* d_in, const int* in_sizes, int n_in,
                              void* d_out, int out_size)
{
    const float* x    = (const float*)d_in[0];
    const float* fw1  = (const float*)d_in[1];
    const float* fb1  = (const float*)d_in[2];
    const float* fw2  = (const float*)d_in[3];
    const float* fb2  = (const float*)d_in[4];
    const float* kw   = (const float*)d_in[5];
    const float* kb   = (const float*)d_in[6];
    const float* keys = (const float*)d_in[7];
    const float* ew1  = (const float*)d_in[8];
    const float* eb1  = (const float*)d_in[9];
    const float* ew2  = (const float*)d_in[10];
    const float* eb2  = (const float*)d_in[11];
    const float* ew3  = (const float*)d_in[12];
    const float* eb3  = (const float*)d_in[13];
    float* out = (float*)d_out;

    cudaFuncSetAttribute(tgemm_k<0, true,  3>, cudaFuncAttributeMaxDynamicSharedMemorySize, TG_SMEM);
    cudaFuncSetAttribute(tgemm_k<1, false, 3>, cudaFuncAttributeMaxDynamicSharedMemorySize, TG_SMEM);
    cudaFuncSetAttribute(tgemm_k<3, true,  1>, cudaFuncAttributeMaxDynamicSharedMemorySize, TG_SMEM);
    cudaFuncSetAttribute(tgemm_k<4, true,  1>, cudaFuncAttributeMaxDynamicSharedMemorySize, TG_SMEM);
    cudaFuncSetAttribute(tgemm_k<5, false, 1>, cudaFuncAttributeMaxDynamicSharedMemorySize, TG_SMEM);

    dim3 blk(256);

    keysn_kernel<<<1, 256>>>(keys);
    zero_counts_kernel<<<1, 32>>>();

    // feature extractor: 3xTF32 split (fp32-grade accuracy for routing)
    tgemm_k<0, true,  3><<<dim3(HDIM / 128, BDIM / 128, 1), blk, TG_SMEM>>>(x,       fw1, fb1, BDIM, HDIM, DDIM);
    tgemm_k<1, false, 3><<<dim3(HDIM / 128, BDIM / 128, 1), blk, TG_SMEM>>>(nullptr, fw2, fb2, BDIM, HDIM, HDIM);

    // router projection: fp32
    gemm_k<2, false><<<dim3(1, BDIM / BM), blk>>>(nullptr, kw, kb, BDIM, KDIM, HDIM);

    router_kernel<<<BDIM / 8, 256>>>();
    scan_kernel<<<1, 32>>>();
    scatter_kernel<<<(BDIM + 255) / 256, 256>>>();

    // expert MLPs: single-pass TF32 on grouped (top-2 only) rows
    tgemm_k<3, true,  1><<<dim3(HDIM / 128,         BDIM / 128, EDIM), blk, TG_SMEM>>>(nullptr, ew1, eb1, 0, HDIM,  HDIM);
    tgemm_k<4, true,  1><<<dim3(H2DIM / 128,        BDIM / 128, EDIM), blk, TG_SMEM>>>(nullptr, ew2, eb2, 0, H2DIM, HDIM);
    tgemm_k<5, false, 1><<<dim3((CDIM + 127) / 128, BDIM / 128, EDIM), blk, TG_SMEM>>>(nullptr, ew3, eb3, 0, CDIM,  H2DIM);

    combine_kernel<<<BDIM, 256>>>(out);
    tail_writer_kernel<<<(BDIM * EDIM + 255) / 256, 256>>>(out, (long long)out_size);
}